// round 10
// baseline (speedup 1.0000x reference)
#include <cuda_runtime.h>
#include <cstdint>

#define BATCH   4
#define KCLS    64
#define NSHOT   32
#define DIM     128
#define MTEST   4096
#define TRN     (KCLS * NSHOT)      // 2048 train rows per batch
#define TM      128                 // test tile per block
#define TN      128                 // train rows per chunk (4 classes)
#define NCHUNK  (TRN / TN)          // 16
#define THREADS 1024                // 32 warps -> 8 warps/SMSP, <=64 regs

// ---------------------------------------------------------------------------
// Fused cosine-sim argmax (exact, verified R7-R9).
//   score(m,n) = dot(test_raw[m], train_raw[n]) * invnorm(train[n])
//   label = first argmax over classes of (max over 32 shots)
// Test normalization dropped (positive scalar, argmax-invariant).
// Inner loop: packed fma.rn.f32x2, thread tile 2 tests x 4 train-pairs
// (8 FFMA2/kk/thread) — sized so 1024 threads fit in 64 regs/thread,
// giving 8 warps/SMSP to hide the 29-cyc LDS latency.
// Output: float32 labels.
// ---------------------------------------------------------------------------

__device__ __forceinline__ void ffma2(unsigned long long& d,
                                      unsigned long long a,
                                      unsigned long long b) {
    asm("fma.rn.f32x2 %0, %1, %2, %0;" : "+l"(d) : "l"(a), "l"(b));
}
__device__ __forceinline__ unsigned long long dup2(float a) {
    unsigned long long r;
    asm("mov.b64 %0, {%1, %1};" : "=l"(r) : "f"(a));
    return r;
}
__device__ __forceinline__ float2 u2f2(unsigned long long u) {
    float2 f;
    asm("mov.b64 {%0, %1}, %2;" : "=f"(f.x), "=f"(f.y) : "l"(u));
    return f;
}

extern __shared__ __align__(16) float smem[];

__global__ __launch_bounds__(THREADS, 1)
void ms_kernel(const float* __restrict__ train,
               const float* __restrict__ test,
               float* __restrict__ out) {
    float* teS   = smem;                    // [128][128] tests  (64 KB)
    float* trS   = smem + DIM * TM;         // [128][128] trains (64 KB)
    float* invnS = smem + 2 * DIM * TM;     // [128]

    const int tid  = threadIdx.x;
    const int lane = tid & 31;
    const int warp = tid >> 5;              // 0..31
    const int tx   = tid & 15;              // train-column group (16 lanes/class)
    const int ty   = tid >> 4;              // test group, 0..63 (2 tests each)
    const int b      = blockIdx.y;
    const int m_base = blockIdx.x * TM;

    const float* teg = test  + ((size_t)b * MTEST + m_base) * DIM;
    const float* trg = train + (size_t)b * TRN * DIM;

    // ---- load test tile once: transposed + swizzled (4 rows per warp) ---
    #pragma unroll
    for (int r = 0; r < 4; ++r) {
        int m = warp * 4 + r;
        float4 v = *(const float4*)(teg + (size_t)m * DIM + lane * 4);
        int m4 = m >> 2, mo = m & 3;
        float vv[4] = {v.x, v.y, v.z, v.w};
        #pragma unroll
        for (int i = 0; i < 4; ++i)
            teS[(lane * 4 + i) * TM + ((m4 ^ lane) << 2) + mo] = vv[i];
    }

    float bestv[2];
    int   bestk[2];
    #pragma unroll
    for (int i = 0; i < 2; ++i) { bestv[i] = -3.402823466e38f; bestk[i] = 0; }

    const int txh = tx >> 1;                // block within class octet (0..7)
    const int txo = (tx & 1) << 1;          // float2 offset within block
    const int tyh = ty >> 1;                // test float4-block (0..31)
    const int tyo = (ty & 1) << 1;          // float2 offset within block

    for (int chunk = 0; chunk < NCHUNK; ++chunk) {
        const int rowBase = chunk * TN;

        __syncthreads();   // iter 0: te ready; else: previous compute done

        // ---- load 128 train rows: transposed + swizzled + row invnorm ---
        #pragma unroll
        for (int r = 0; r < 4; ++r) {
            int n = warp * 4 + r;
            float4 v = *(const float4*)(trg + (size_t)(rowBase + n) * DIM + lane * 4);
            float s = v.x * v.x + v.y * v.y + v.z * v.z + v.w * v.w;
            #pragma unroll
            for (int o = 16; o; o >>= 1) s += __shfl_xor_sync(0xffffffffu, s, o);
            if (lane == 0) invnS[n] = 1.0f / fmaxf(sqrtf(s), 1e-8f);

            int n4 = n >> 2, no = n & 3;
            float vv[4] = {v.x, v.y, v.z, v.w};
            #pragma unroll
            for (int i = 0; i < 4; ++i)
                trS[(lane * 4 + i) * TN + ((n4 ^ lane) << 2) + no] = vv[i];
        }
        __syncthreads();

        // ---- FFMA2 mainloop: 2 tests x 4 train-pairs per thread ---------
        // acc2[i][q] = packed (score(test 2ty+i, shot 2tx   of class q),
        //                      score(test 2ty+i, shot 2tx+1 of class q))
        unsigned long long acc2[2][4];
        #pragma unroll
        for (int i = 0; i < 2; ++i)
            #pragma unroll
            for (int j = 0; j < 4; ++j) acc2[i][j] = 0ULL;

        // outer: swizzle phase s = kk>>2 (addresses constant per phase);
        // inner: 4 kk with immediate-offset loads
        #pragma unroll 2
        for (int s = 0; s < DIM / 4; ++s) {
            const float* aP  = teS + (s * 4) * TM + ((tyh ^ s) << 2) + tyo;
            const float* bP0 = trS + (s * 4) * TN + ((( 0 + txh) ^ s) << 2) + txo;
            const float* bP1 = trS + (s * 4) * TN + ((( 8 + txh) ^ s) << 2) + txo;
            const float* bP2 = trS + (s * 4) * TN + (((16 + txh) ^ s) << 2) + txo;
            const float* bP3 = trS + (s * 4) * TN + (((24 + txh) ^ s) << 2) + txo;

            #pragma unroll
            for (int u = 0; u < 4; ++u) {
                float2 a = *(const float2*)(aP + u * TM);   // tests 2ty, 2ty+1
                unsigned long long B2[4];
                B2[0] = *(const unsigned long long*)(bP0 + u * TN);
                B2[1] = *(const unsigned long long*)(bP1 + u * TN);
                B2[2] = *(const unsigned long long*)(bP2 + u * TN);
                B2[3] = *(const unsigned long long*)(bP3 + u * TN);

                unsigned long long A2[2];
                A2[0] = dup2(a.x);
                A2[1] = dup2(a.y);

                #pragma unroll
                for (int i = 0; i < 2; ++i)
                    #pragma unroll
                    for (int j = 0; j < 4; ++j)
                        ffma2(acc2[i][j], A2[i], B2[j]);
            }
        }

        // ---- fold inv-norms, class max over 32 shots (16 lanes x 2),
        //      running argmax (ascending class order, strict > = first-max)
        #pragma unroll
        for (int q = 0; q < 4; ++q) {
            float w0 = invnS[q * 32 + 2 * tx];
            float w1 = invnS[q * 32 + 2 * tx + 1];
            #pragma unroll
            for (int i = 0; i < 2; ++i) {
                float2 f = u2f2(acc2[i][q]);
                float v = fmaxf(f.x * w0, f.y * w1);
                #pragma unroll
                for (int o = 1; o <= 8; o <<= 1)   // reduce across 16 tx lanes
                    v = fmaxf(v, __shfl_xor_sync(0xffffffffu, v, o));
                int cls = chunk * 4 + q;
                if (v > bestv[i]) { bestv[i] = v; bestk[i] = cls; }
            }
        }
    }

    // all 16 tx lanes hold identical results; tx==0 writes its 2 tests
    if (tx == 0) {
        float* o = out + ((size_t)b * MTEST + m_base + ty * 2);
        o[0] = (float)bestk[0];
        o[1] = (float)bestk[1];
    }
}

// ---------------------------------------------------------------------------
extern "C" void kernel_launch(void* const* d_in, const int* in_sizes, int n_in,
                              void* d_out, int out_size) {
    const float* train;
    const float* test;
    if (in_sizes[0] == BATCH * KCLS * NSHOT * DIM) {
        train = (const float*)d_in[0];
        test  = (const float*)d_in[1];
    } else {
        train = (const float*)d_in[1];
        test  = (const float*)d_in[0];
    }
    float* out = (float*)d_out;

    const int smem_bytes = (2 * DIM * TM + TN) * (int)sizeof(float); // ~128.5 KB
    cudaFuncSetAttribute(ms_kernel,
                         cudaFuncAttributeMaxDynamicSharedMemorySize,
                         smem_bytes);

    dim3 grid(MTEST / TM, BATCH);
    ms_kernel<<<grid, THREADS, smem_bytes>>>(train, test, out);
}

// round 11
// speedup vs baseline: 1.4487x; 1.4487x over previous
#include <cuda_runtime.h>
#include <cstdint>

#define BATCH   4
#define KCLS    64
#define NSHOT   32
#define DIM     128
#define MTEST   4096
#define TRN     (KCLS * NSHOT)      // 2048 train rows per batch
#define TM      128                 // test tile per block
#define TN      128                 // train rows per chunk (4 classes)
#define NCHUNK  (TRN / TN)          // 16
#define THREADS 512                 // 16 warps -> 4 warps/SMSP (pipe-capped point)

// ---------------------------------------------------------------------------
// Fused cosine-sim argmax (exact, verified R7-R10).
//   score(m,n) = dot(test_raw[m], train_raw[n]) * invnorm(train[n])
//   label = first argmax over classes of (max over 32 shots)
// Test normalization dropped (positive scalar, argmax-invariant).
//
// R11: R9 tiling (4 tests x 4 train-pairs / thread, 512 threads), mainloop
// restructured into load-phase / compute-phase per swizzle group of 4 kk:
// all 20 smem loads issue back-to-back before the 64 FFMA2s, burying the
// 29-cyc LDS latency under the previous FMA block.
// Output: float32 labels.
// ---------------------------------------------------------------------------

typedef unsigned long long ull;

__device__ __forceinline__ void ffma2(ull& d, ull a, ull b) {
    asm("fma.rn.f32x2 %0, %1, %2, %0;" : "+l"(d) : "l"(a), "l"(b));
}
__device__ __forceinline__ ull dup2(float a) {
    ull r;
    asm("mov.b64 %0, {%1, %1};" : "=l"(r) : "f"(a));
    return r;
}
__device__ __forceinline__ float2 u2f2(ull u) {
    float2 f;
    asm("mov.b64 {%0, %1}, %2;" : "=f"(f.x), "=f"(f.y) : "l"(u));
    return f;
}

extern __shared__ __align__(16) float smem[];

__global__ __launch_bounds__(THREADS, 1)
void ms_kernel(const float* __restrict__ train,
               const float* __restrict__ test,
               float* __restrict__ out) {
    float* teS   = smem;                    // [128][128] tests  (64 KB)
    float* trS   = smem + DIM * TM;         // [128][128] trains (64 KB)
    float* invnS = smem + 2 * DIM * TM;     // [128]

    const int tid  = threadIdx.x;
    const int lane = tid & 31;
    const int warp = tid >> 5;              // 0..15
    const int tx   = tid & 15;              // train-column group (16 lanes/class)
    const int ty   = tid >> 4;              // test group, 0..31 (4 tests each)
    const int b      = blockIdx.y;
    const int m_base = blockIdx.x * TM;

    const float* teg = test  + ((size_t)b * MTEST + m_base) * DIM;
    const float* trg = train + (size_t)b * TRN * DIM;

    // ---- load test tile once: transposed + swizzled (8 rows per warp) ---
    #pragma unroll
    for (int r = 0; r < 8; ++r) {
        int m = warp * 8 + r;
        float4 v = *(const float4*)(teg + (size_t)m * DIM + lane * 4);
        int m4 = m >> 2, mo = m & 3;
        float vv[4] = {v.x, v.y, v.z, v.w};
        #pragma unroll
        for (int i = 0; i < 4; ++i)
            teS[(lane * 4 + i) * TM + ((m4 ^ lane) << 2) + mo] = vv[i];
    }

    float bestv[4];
    int   bestk[4];
    #pragma unroll
    for (int i = 0; i < 4; ++i) { bestv[i] = -3.402823466e38f; bestk[i] = 0; }

    const int txh = tx >> 1;                // block within class octet (0..7)
    const int txo = (tx & 1) << 1;          // float2 offset within block

    for (int chunk = 0; chunk < NCHUNK; ++chunk) {
        const int rowBase = chunk * TN;

        __syncthreads();   // iter 0: te ready; else: previous compute done

        // ---- load 128 train rows: transposed + swizzled + row invnorm ---
        #pragma unroll
        for (int r = 0; r < 8; ++r) {
            int n = warp * 8 + r;
            float4 v = *(const float4*)(trg + (size_t)(rowBase + n) * DIM + lane * 4);
            float s = v.x * v.x + v.y * v.y + v.z * v.z + v.w * v.w;
            #pragma unroll
            for (int o = 16; o; o >>= 1) s += __shfl_xor_sync(0xffffffffu, s, o);
            if (lane == 0) invnS[n] = 1.0f / fmaxf(sqrtf(s), 1e-8f);

            int n4 = n >> 2, no = n & 3;
            float vv[4] = {v.x, v.y, v.z, v.w};
            #pragma unroll
            for (int i = 0; i < 4; ++i)
                trS[(lane * 4 + i) * TN + ((n4 ^ lane) << 2) + no] = vv[i];
        }
        __syncthreads();

        // ---- FFMA2 mainloop: 4 tests x 4 train-pairs per thread ---------
        // acc2[i][q] = packed (score(test 4ty+i, shot 2tx   of class q),
        //                      score(test 4ty+i, shot 2tx+1 of class q))
        ull acc2[4][4];
        #pragma unroll
        for (int i = 0; i < 4; ++i)
            #pragma unroll
            for (int j = 0; j < 4; ++j) acc2[i][j] = 0ULL;

        // per phase s (4 kk): LOAD PHASE (20 loads) then COMPUTE PHASE
        #pragma unroll 2
        for (int s = 0; s < DIM / 4; ++s) {
            const float* teB = teS + (s * 4) * TM + ((ty ^ s) << 2);
            const float* trB = trS + (s * 4) * TN;
            const int ob0 = ((( 0 + txh) ^ s) << 2) + txo;
            const int ob1 = ((( 8 + txh) ^ s) << 2) + txo;
            const int ob2 = (((16 + txh) ^ s) << 2) + txo;
            const int ob3 = (((24 + txh) ^ s) << 2) + txo;

            float4 A[4];
            ull    B[4][4];
            #pragma unroll
            for (int u = 0; u < 4; ++u) {
                A[u]    = *(const float4*)(teB + u * TM);
                B[u][0] = *(const ull*)(trB + u * TN + ob0);
                B[u][1] = *(const ull*)(trB + u * TN + ob1);
                B[u][2] = *(const ull*)(trB + u * TN + ob2);
                B[u][3] = *(const ull*)(trB + u * TN + ob3);
            }

            #pragma unroll
            for (int u = 0; u < 4; ++u) {
                ull A2[4] = {dup2(A[u].x), dup2(A[u].y),
                             dup2(A[u].z), dup2(A[u].w)};
                #pragma unroll
                for (int i = 0; i < 4; ++i)
                    #pragma unroll
                    for (int j = 0; j < 4; ++j)
                        ffma2(acc2[i][j], A2[i], B[u][j]);
            }
        }

        // ---- fold inv-norms, class max over 32 shots (16 lanes x 2),
        //      running argmax (ascending class order, strict > = first-max)
        float w[8];
        #pragma unroll
        for (int q = 0; q < 4; ++q) {
            w[2 * q]     = invnS[q * 32 + 2 * tx];
            w[2 * q + 1] = invnS[q * 32 + 2 * tx + 1];
        }

        #pragma unroll
        for (int i = 0; i < 4; ++i) {
            #pragma unroll
            for (int q = 0; q < 4; ++q) {
                float2 f = u2f2(acc2[i][q]);
                float v = fmaxf(f.x * w[2 * q], f.y * w[2 * q + 1]);
                #pragma unroll
                for (int o = 1; o <= 8; o <<= 1)   // reduce across 16 tx lanes
                    v = fmaxf(v, __shfl_xor_sync(0xffffffffu, v, o));
                int cls = chunk * 4 + q;
                if (v > bestv[i]) { bestv[i] = v; bestk[i] = cls; }
            }
        }
    }

    // all 16 tx lanes hold identical results; tx==0 writes its 4 tests
    if (tx == 0) {
        float* o = out + ((size_t)b * MTEST + m_base + ty * 4);
        #pragma unroll
        for (int i = 0; i < 4; ++i) o[i] = (float)bestk[i];
    }
}

// ---------------------------------------------------------------------------
extern "C" void kernel_launch(void* const* d_in, const int* in_sizes, int n_in,
                              void* d_out, int out_size) {
    const float* train;
    const float* test;
    if (in_sizes[0] == BATCH * KCLS * NSHOT * DIM) {
        train = (const float*)d_in[0];
        test  = (const float*)d_in[1];
    } else {
        train = (const float*)d_in[1];
        test  = (const float*)d_in[0];
    }
    float* out = (float*)d_out;

    const int smem_bytes = (2 * DIM * TM + TN) * (int)sizeof(float); // ~128.5 KB
    cudaFuncSetAttribute(ms_kernel,
                         cudaFuncAttributeMaxDynamicSharedMemorySize,
                         smem_bytes);

    dim3 grid(MTEST / TM, BATCH);
    ms_kernel<<<grid, THREADS, smem_bytes>>>(train, test, out);
}